// round 9
// baseline (speedup 1.0000x reference)
#include <cuda_runtime.h>

// LSTM2LINEAR: B=8192, T=1024, H=10, scalar input.
// Gate-split lane pairs: element (batch,r) = 2 lanes.
//   even lane: f32x2 accumulator {i/2, f/2}
//   odd  lane: f32x2 accumulator {g,   o/2}
// Each lane: ONE 11-deep fma2 dot (weights in regs), 2 tanh on its halves,
// then shfl.xor(1) exchanges (tg,to) odd->even. Even lanes update c and write
// doubled h; odd lanes run the same instrs on dead data (no divergence).
// Block = 5 warps = 160 lanes = 80 elems = 8 batches (0 idle lanes).
// h exchanged as {2h,2h} ull pairs in block smem, 1 __syncthreads/step.
// Warps: 5120 (8.65/SMSP) -- 1.9x more than the 3-batch/warp layout, same
// total FMA work => better latency hiding against the ~276cyc/SMSP FMA floor.

#define T_STEPS 1024
#define HDIM 10
#define NB 8                      // batches per block
#define NTH 160                   // 5 warps

typedef unsigned long long ull;

__device__ __forceinline__ ull pk(float lo, float hi) {
    ull v;
    asm("mov.b64 %0, {%1, %2};" : "=l"(v)
        : "r"(__float_as_uint(lo)), "r"(__float_as_uint(hi)));
    return v;
}
__device__ __forceinline__ float2 upk(ull v) {
    unsigned int lo, hi;
    asm("mov.b64 {%0, %1}, %2;" : "=r"(lo), "=r"(hi) : "l"(v));
    return make_float2(__uint_as_float(lo), __uint_as_float(hi));
}
__device__ __forceinline__ ull fma2(ull a, ull b, ull c) {
    ull d;
    asm("fma.rn.f32x2 %0, %1, %2, %3;" : "=l"(d) : "l"(a), "l"(b), "l"(c));
    return d;
}
__device__ __forceinline__ ull mul2(ull a, ull b) {
    ull d;
    asm("mul.rn.f32x2 %0, %1, %2;" : "=l"(d) : "l"(a), "l"(b));
    return d;
}
__device__ __forceinline__ ull add2(ull a, ull b) {
    ull d;
    asm("add.rn.f32x2 %0, %1, %2;" : "=l"(d) : "l"(a), "l"(b));
    return d;
}
__device__ __forceinline__ float tanha(float x) {
    float y; asm("tanh.approx.f32 %0, %1;" : "=f"(y) : "f"(x)); return y;
}

__global__ void __launch_bounds__(NTH)
lstm2linear_kernel(const float* __restrict__ x,      // [B, T]
                   const float* __restrict__ W_ih,   // [4H, 1]
                   const float* __restrict__ W_hh,   // [4H, H]
                   const float* __restrict__ b_ih,   // [4H]
                   const float* __restrict__ b_hh,   // [4H]
                   const float* __restrict__ W_lin,  // [1, H]
                   const float* __restrict__ b_lin,  // [1]
                   float* __restrict__ out)          // [B]
{
    // hs[buf][batch][j] = {2h_j, 2h_j}. Row = 80B (5x16B), 16B-aligned.
    __shared__ ull hs[2][NB][HDIM];

    const int tid  = threadIdx.x;
    const int e    = tid >> 1;            // element 0..79
    const int half = tid & 1;             // 0: (i,f)  1: (g,o)
    const int bl   = e / HDIM;            // local batch 0..7
    const int r    = e % HDIM;            // hidden elem 0..9
    const int b    = blockIdx.x * NB + bl;

    // Gate rows / scales for this lane:
    //   W_hh folding: x0.5 (h stored doubled) and x0.5 (sigmoid half-arg for i,f,o)
    //   W_ih & bias:  x0.5 sigmoid half-arg for i,f,o only.
    const int   gLo  = half ? 2 : 0;          // g : i
    const int   gHi  = half ? 3 : 1;          // o : f
    const float shLo = half ? 0.5f  : 0.25f;  // W_hh scale
    const float shHi = 0.25f;
    const float sxLo = half ? 1.0f  : 0.5f;   // W_ih/bias scale
    const float sxHi = 0.5f;

    ull w[HDIM];
#pragma unroll
    for (int j = 0; j < HDIM; j++) {
        w[j] = pk(shLo * W_hh[(gLo * HDIM + r) * HDIM + j],
                  shHi * W_hh[(gHi * HDIM + r) * HDIM + j]);
    }
    const ull u2 = pk(sxLo * W_ih[gLo * HDIM + r],
                      sxHi * W_ih[gHi * HDIM + r]);
    const ull b2 = pk(sxLo * (b_ih[gLo * HDIM + r] + b_hh[gLo * HDIM + r]),
                      sxHi * (b_ih[gHi * HDIM + r] + b_hh[gHi * HDIM + r]));
    const float wlin = W_lin[r];

    float c = 0.0f;

    // zero both h buffers: 2*8*10 = 160 ulls, exactly one per lane
    (&hs[0][0][0])[tid] = 0ull;
    __syncthreads();

    const float* xb = x + (size_t)b * T_STEPS;
    int p = 0;

    float4 xv = *reinterpret_cast<const float4*>(xb);

    for (int t0 = 0; t0 < T_STEPS; t0 += 4) {
        const int tn = (t0 + 4 < T_STEPS) ? (t0 + 4) : t0;
        const float4 xn = *reinterpret_cast<const float4*>(xb + tn);
#pragma unroll
        for (int k = 0; k < 4; k++) {
            const float xt = (k == 0) ? xv.x : (k == 1) ? xv.y :
                             (k == 2) ? xv.z : xv.w;
            const ull xx = pk(xt, xt);

            const ulonglong2* hp =
                reinterpret_cast<const ulonglong2*>(&hs[p][bl][0]);
            const ulonglong2 q0 = hp[0], q1 = hp[1], q2 = hp[2],
                             q3 = hp[3], q4 = hp[4];

            // one gate-pair dot per lane, split 6+5 for shorter dep chain
            ull ca = fma2(xx, u2, b2);
            ca = fma2(w[0], q0.x, ca);
            ca = fma2(w[1], q0.y, ca);
            ca = fma2(w[2], q1.x, ca);
            ca = fma2(w[3], q1.y, ca);
            ca = fma2(w[4], q2.x, ca);
            ull cb = mul2(w[5], q2.y);
            cb = fma2(w[6], q3.x, cb);
            cb = fma2(w[7], q3.y, cb);
            cb = fma2(w[8], q4.x, cb);
            cb = fma2(w[9], q4.y, cb);
            const ull acc = add2(ca, cb);

            // even lane: acc = {i/2, f/2};  odd lane: acc = {g, o/2}
            const float2 av = upk(acc);
            const float tLo = tanha(av.x);       // even: tanh(i/2)  odd: tanh(g)
            const float tHi = tanha(av.y);       // even: tanh(f/2)  odd: tanh(o/2)

            // exchange partner's values (even lanes receive tg, to)
            const float tx = __shfl_xor_sync(0xffffffffu, tLo, 1);
            const float ty = __shfl_xor_sync(0xffffffffu, tHi, 1);

            // even lanes compute the recurrence (odd lanes: dead data, same instrs)
            const float si = fmaf(0.5f, tLo, 0.5f);
            const float sf = fmaf(0.5f, tHi, 0.5f);
            c = fmaf(sf, c, si * tx);

            const float tc = tanha(c);
            const float hn2 = fmaf(ty, tc, tc);   // 2h = (sigmoid(o)*2)*tanh(c)

            if (half == 0) hs[p ^ 1][bl][r] = pk(hn2, hn2);
            __syncthreads();
            p ^= 1;
        }
        xv = xn;
    }

    // ---- output: out[b] = sum_r c_r * W_lin[r] + b_lin ----
    float* scr = reinterpret_cast<float*>(&hs[0][0][0]);
    if (half == 0) scr[bl * HDIM + r] = c * wlin;
    __syncthreads();
    if (tid < NB) {
        float s = b_lin[0];
#pragma unroll
        for (int j = 0; j < HDIM; j++) s += scr[tid * HDIM + j];
        out[blockIdx.x * NB + tid] = s;
    }
}

extern "C" void kernel_launch(void* const* d_in, const int* in_sizes, int n_in,
                              void* d_out, int out_size) {
    const float* x     = (const float*)d_in[0];  // [B, T, 1]
    const float* W_ih  = (const float*)d_in[1];  // [4H, 1]
    const float* W_hh  = (const float*)d_in[2];  // [4H, H]
    const float* b_ih  = (const float*)d_in[3];  // [4H]
    const float* b_hh  = (const float*)d_in[4];  // [4H]
    const float* W_lin = (const float*)d_in[5];  // [1, H]
    const float* b_lin = (const float*)d_in[6];  // [1]
    float* out = (float*)d_out;                  // [B, 1]

    const int B = in_sizes[0] / T_STEPS;         // 8192
    const int blocks = B / NB;                   // 1024 blocks x 5 warps

    lstm2linear_kernel<<<blocks, NTH>>>(x, W_ih, W_hh, b_ih, b_hh,
                                        W_lin, b_lin, out);
}

// round 10
// speedup vs baseline: 1.0716x; 1.0716x over previous
#include <cuda_runtime.h>

// LSTM2LINEAR: B=8192, T=1024, H=10, scalar input.
// Gate-split lane pairs (R9 layout, 5120 warps) + even/odd-pair packing:
//   even lane: gates (i, f);  odd lane: gates (g, o).
//   Per gate: acc2 = {Sum_even w_j h_j, Sum_odd w_j h_j} via 5 fma2 against
//   NATURAL {h_2k, h_2k+1} pairs from LDS.128 (no duplicated-h storage),
//   initialized with mul2({x,1},{u,b}) so one horizontal add finishes the gate.
// h stored PLAIN (40B/row, doubled value 2h; 0.5 folded into W_hh) -> LDS
// traffic halved vs R9 (the 82.5%-saturated pipe).
// tanh.approx nonlinearities; pair exchange via 2x shfl.xor(1);
// block = 5 warps = 8 batches, one __syncthreads per step.

#define T_STEPS 1024
#define HDIM 10
#define NB 8                      // batches per block
#define NTH 160                   // 5 warps

typedef unsigned long long ull;

__device__ __forceinline__ ull pk(float lo, float hi) {
    ull v;
    asm("mov.b64 %0, {%1, %2};" : "=l"(v)
        : "r"(__float_as_uint(lo)), "r"(__float_as_uint(hi)));
    return v;
}
__device__ __forceinline__ float2 upk(ull v) {
    unsigned int lo, hi;
    asm("mov.b64 {%0, %1}, %2;" : "=r"(lo), "=r"(hi) : "l"(v));
    return make_float2(__uint_as_float(lo), __uint_as_float(hi));
}
__device__ __forceinline__ ull fma2(ull a, ull b, ull c) {
    ull d;
    asm("fma.rn.f32x2 %0, %1, %2, %3;" : "=l"(d) : "l"(a), "l"(b), "l"(c));
    return d;
}
__device__ __forceinline__ ull mul2(ull a, ull b) {
    ull d;
    asm("mul.rn.f32x2 %0, %1, %2;" : "=l"(d) : "l"(a), "l"(b));
    return d;
}
__device__ __forceinline__ float tanha(float x) {
    float y; asm("tanh.approx.f32 %0, %1;" : "=f"(y) : "f"(x)); return y;
}

__global__ void __launch_bounds__(NTH)
lstm2linear_kernel(const float* __restrict__ x,      // [B, T]
                   const float* __restrict__ W_ih,   // [4H, 1]
                   const float* __restrict__ W_hh,   // [4H, H]
                   const float* __restrict__ b_ih,   // [4H]
                   const float* __restrict__ b_hh,   // [4H]
                   const float* __restrict__ W_lin,  // [1, H]
                   const float* __restrict__ b_lin,  // [1]
                   float* __restrict__ out)          // [B]
{
    // hs[buf][batch][j] = 2h_j (plain float). Row padded to 12 (48B, 16B-aligned).
    __shared__ float hs[2][NB][12];

    const int tid  = threadIdx.x;
    const int e    = tid >> 1;            // element 0..79
    const int half = tid & 1;             // 0: (i,f)  1: (g,o)
    const int bl   = e / HDIM;            // local batch 0..7
    const int r    = e % HDIM;            // hidden elem 0..9
    const int b    = blockIdx.x * NB + bl;

    // Scales: W_hh gets x0.5 for doubled-h on ALL rows, plus x0.5 sigmoid
    // half-arg on i,f,o rows. W_ih/bias get x0.5 half-arg on i,f,o only.
    const int   gLo  = half ? 2 : 0;          // g : i
    const int   gHi  = half ? 3 : 1;          // o : f
    const float shLo = half ? 0.5f  : 0.25f;  // W_hh scale, low gate
    const float shHi = 0.25f;                 // W_hh scale, high gate (f or o)
    const float sxLo = half ? 1.0f  : 0.5f;   // W_ih/bias scale, low gate
    const float sxHi = 0.5f;

    // even/odd weight pairs: wLo[k] = {w_2k, w_2k+1} of gate gLo (scaled)
    ull wLo[5], wHi[5];
#pragma unroll
    for (int k = 0; k < 5; k++) {
        wLo[k] = pk(shLo * W_hh[(gLo * HDIM + r) * HDIM + 2 * k],
                    shLo * W_hh[(gLo * HDIM + r) * HDIM + 2 * k + 1]);
        wHi[k] = pk(shHi * W_hh[(gHi * HDIM + r) * HDIM + 2 * k],
                    shHi * W_hh[(gHi * HDIM + r) * HDIM + 2 * k + 1]);
    }
    // {u, b} packed: init acc = mul2({x,1},{u,b}) = {x*u, b}
    const ull ubLo = pk(sxLo * W_ih[gLo * HDIM + r],
                        sxLo * (b_ih[gLo * HDIM + r] + b_hh[gLo * HDIM + r]));
    const ull ubHi = pk(sxHi * W_ih[gHi * HDIM + r],
                        sxHi * (b_ih[gHi * HDIM + r] + b_hh[gHi * HDIM + r]));
    const float wlin = W_lin[r];

    float c = 0.0f;

    // zero both h buffers: 2*8*12 = 192 floats
    for (int i = tid; i < 2 * NB * 12; i += NTH)
        (&hs[0][0][0])[i] = 0.0f;
    __syncthreads();

    const float* xb = x + (size_t)b * T_STEPS;
    int p = 0;

    float4 xv = *reinterpret_cast<const float4*>(xb);

    for (int t0 = 0; t0 < T_STEPS; t0 += 4) {
        const int tn = (t0 + 4 < T_STEPS) ? (t0 + 4) : t0;
        const float4 xn = *reinterpret_cast<const float4*>(xb + tn);
#pragma unroll
        for (int k = 0; k < 4; k++) {
            const float xt = (k == 0) ? xv.x : (k == 1) ? xv.y :
                             (k == 2) ? xv.z : xv.w;
            const ull x1 = pk(xt, 1.0f);

            // natural h pairs: 40B per lane (2x LDS.128 + 1x LDS.64)
            const float4 ha = *reinterpret_cast<const float4*>(&hs[p][bl][0]);
            const float4 hb = *reinterpret_cast<const float4*>(&hs[p][bl][4]);
            const float2 hc = *reinterpret_cast<const float2*>(&hs[p][bl][8]);
            const ull h01 = pk(ha.x, ha.y);
            const ull h23 = pk(ha.z, ha.w);
            const ull h45 = pk(hb.x, hb.y);
            const ull h67 = pk(hb.z, hb.w);
            const ull h89 = pk(hc.x, hc.y);

            // two gates per lane, 5 fma2 each on natural pairs
            ull aLo = mul2(x1, ubLo);          // {x*u, b}
            aLo = fma2(wLo[0], h01, aLo);
            aLo = fma2(wLo[1], h23, aLo);
            aLo = fma2(wLo[2], h45, aLo);
            aLo = fma2(wLo[3], h67, aLo);
            aLo = fma2(wLo[4], h89, aLo);
            ull aHi = mul2(x1, ubHi);
            aHi = fma2(wHi[0], h01, aHi);
            aHi = fma2(wHi[1], h23, aHi);
            aHi = fma2(wHi[2], h45, aHi);
            aHi = fma2(wHi[3], h67, aHi);
            aHi = fma2(wHi[4], h89, aHi);

            const float2 vLo = upk(aLo);
            const float2 vHi = upk(aHi);
            const float gateLo = vLo.x + vLo.y;  // even: i/2   odd: g
            const float gateHi = vHi.x + vHi.y;  // even: f/2   odd: o/2

            const float tLo = tanha(gateLo);
            const float tHi = tanha(gateHi);

            // exchange partner's tanh values (even lanes receive tg, to)
            const float tx = __shfl_xor_sync(0xffffffffu, tLo, 1);
            const float ty = __shfl_xor_sync(0xffffffffu, tHi, 1);

            // even lanes: real recurrence (odd lanes same instrs, dead data)
            const float si = fmaf(0.5f, tLo, 0.5f);
            const float sf = fmaf(0.5f, tHi, 0.5f);
            c = fmaf(sf, c, si * tx);

            const float tc = tanha(c);
            const float hn2 = fmaf(ty, tc, tc);   // 2h = (tanh(o/2)+1)*tanh(c)

            if (half == 0) hs[p ^ 1][bl][r] = hn2;
            __syncthreads();
            p ^= 1;
        }
        xv = xn;
    }

    // ---- output: out[b] = sum_r c_r * W_lin[r] + b_lin ----
    float* scr = &hs[0][0][0];
    if (half == 0) scr[bl * 12 + r] = c * wlin;
    __syncthreads();
    if (tid < NB) {
        float s = b_lin[0];
#pragma unroll
        for (int j = 0; j < HDIM; j++) s += scr[tid * 12 + j];
        out[blockIdx.x * NB + tid] = s;
    }
}

extern "C" void kernel_launch(void* const* d_in, const int* in_sizes, int n_in,
                              void* d_out, int out_size) {
    const float* x     = (const float*)d_in[0];  // [B, T, 1]
    const float* W_ih  = (const float*)d_in[1];  // [4H, 1]
    const float* W_hh  = (const float*)d_in[2];  // [4H, H]
    const float* b_ih  = (const float*)d_in[3];  // [4H]
    const float* b_hh  = (const float*)d_in[4];  // [4H]
    const float* W_lin = (const float*)d_in[5];  // [1, H]
    const float* b_lin = (const float*)d_in[6];  // [1]
    float* out = (float*)d_out;                  // [B, 1]

    const int B = in_sizes[0] / T_STEPS;         // 8192
    const int blocks = B / NB;                   // 1024 blocks x 5 warps

    lstm2linear_kernel<<<blocks, NTH>>>(x, W_ih, W_hh, b_ih, b_hh,
                                        W_lin, b_lin, out);
}

// round 15
// speedup vs baseline: 1.0737x; 1.0020x over previous
#include <cuda_runtime.h>

// LSTM2LINEAR: B=8192, T=1024, H=10, scalar input.
// Gate-split lane pairs (R9 layout, 5120 warps) + even/odd-pair packing:
//   even lane: gates (i, f);  odd lane: gates (g, o).
//   Per gate: acc2 = {Sum_even w_j h_j, Sum_odd w_j h_j} via 5 fma2 against
//   NATURAL {h_2k, h_2k+1} pairs from LDS.128 (no duplicated-h storage),
//   initialized with mul2({x,1},{u,b}) so one horizontal add finishes the gate.
// h stored PLAIN (40B/row, doubled value 2h; 0.5 folded into W_hh) -> LDS
// traffic halved vs R9 (the 82.5%-saturated pipe).
// tanh.approx nonlinearities; pair exchange via 2x shfl.xor(1);
// block = 5 warps = 8 batches, one __syncthreads per step.

#define T_STEPS 1024
#define HDIM 10
#define NB 8                      // batches per block
#define NTH 160                   // 5 warps

typedef unsigned long long ull;

__device__ __forceinline__ ull pk(float lo, float hi) {
    ull v;
    asm("mov.b64 %0, {%1, %2};" : "=l"(v)
        : "r"(__float_as_uint(lo)), "r"(__float_as_uint(hi)));
    return v;
}
__device__ __forceinline__ float2 upk(ull v) {
    unsigned int lo, hi;
    asm("mov.b64 {%0, %1}, %2;" : "=r"(lo), "=r"(hi) : "l"(v));
    return make_float2(__uint_as_float(lo), __uint_as_float(hi));
}
__device__ __forceinline__ ull fma2(ull a, ull b, ull c) {
    ull d;
    asm("fma.rn.f32x2 %0, %1, %2, %3;" : "=l"(d) : "l"(a), "l"(b), "l"(c));
    return d;
}
__device__ __forceinline__ ull mul2(ull a, ull b) {
    ull d;
    asm("mul.rn.f32x2 %0, %1, %2;" : "=l"(d) : "l"(a), "l"(b));
    return d;
}
__device__ __forceinline__ float tanha(float x) {
    float y; asm("tanh.approx.f32 %0, %1;" : "=f"(y) : "f"(x)); return y;
}

__global__ void __launch_bounds__(NTH)
lstm2linear_kernel(const float* __restrict__ x,      // [B, T]
                   const float* __restrict__ W_ih,   // [4H, 1]
                   const float* __restrict__ W_hh,   // [4H, H]
                   const float* __restrict__ b_ih,   // [4H]
                   const float* __restrict__ b_hh,   // [4H]
                   const float* __restrict__ W_lin,  // [1, H]
                   const float* __restrict__ b_lin,  // [1]
                   float* __restrict__ out)          // [B]
{
    // hs[buf][batch][j] = 2h_j (plain float). Row padded to 12 (48B, 16B-aligned).
    __shared__ float hs[2][NB][12];

    const int tid  = threadIdx.x;
    const int e    = tid >> 1;            // element 0..79
    const int half = tid & 1;             // 0: (i,f)  1: (g,o)
    const int bl   = e / HDIM;            // local batch 0..7
    const int r    = e % HDIM;            // hidden elem 0..9
    const int b    = blockIdx.x * NB + bl;

    // Scales: W_hh gets x0.5 for doubled-h on ALL rows, plus x0.5 sigmoid
    // half-arg on i,f,o rows. W_ih/bias get x0.5 half-arg on i,f,o only.
    const int   gLo  = half ? 2 : 0;          // g : i
    const int   gHi  = half ? 3 : 1;          // o : f
    const float shLo = half ? 0.5f  : 0.25f;  // W_hh scale, low gate
    const float shHi = 0.25f;                 // W_hh scale, high gate (f or o)
    const float sxLo = half ? 1.0f  : 0.5f;   // W_ih/bias scale, low gate
    const float sxHi = 0.5f;

    // even/odd weight pairs: wLo[k] = {w_2k, w_2k+1} of gate gLo (scaled)
    ull wLo[5], wHi[5];
#pragma unroll
    for (int k = 0; k < 5; k++) {
        wLo[k] = pk(shLo * W_hh[(gLo * HDIM + r) * HDIM + 2 * k],
                    shLo * W_hh[(gLo * HDIM + r) * HDIM + 2 * k + 1]);
        wHi[k] = pk(shHi * W_hh[(gHi * HDIM + r) * HDIM + 2 * k],
                    shHi * W_hh[(gHi * HDIM + r) * HDIM + 2 * k + 1]);
    }
    // {u, b} packed: init acc = mul2({x,1},{u,b}) = {x*u, b}
    const ull ubLo = pk(sxLo * W_ih[gLo * HDIM + r],
                        sxLo * (b_ih[gLo * HDIM + r] + b_hh[gLo * HDIM + r]));
    const ull ubHi = pk(sxHi * W_ih[gHi * HDIM + r],
                        sxHi * (b_ih[gHi * HDIM + r] + b_hh[gHi * HDIM + r]));
    const float wlin = W_lin[r];

    float c = 0.0f;

    // zero both h buffers: 2*8*12 = 192 floats
    for (int i = tid; i < 2 * NB * 12; i += NTH)
        (&hs[0][0][0])[i] = 0.0f;
    __syncthreads();

    const float* xb = x + (size_t)b * T_STEPS;
    int p = 0;

    float4 xv = *reinterpret_cast<const float4*>(xb);

    for (int t0 = 0; t0 < T_STEPS; t0 += 4) {
        const int tn = (t0 + 4 < T_STEPS) ? (t0 + 4) : t0;
        const float4 xn = *reinterpret_cast<const float4*>(xb + tn);
#pragma unroll
        for (int k = 0; k < 4; k++) {
            const float xt = (k == 0) ? xv.x : (k == 1) ? xv.y :
                             (k == 2) ? xv.z : xv.w;
            const ull x1 = pk(xt, 1.0f);

            // natural h pairs: 40B per lane (2x LDS.128 + 1x LDS.64)
            const float4 ha = *reinterpret_cast<const float4*>(&hs[p][bl][0]);
            const float4 hb = *reinterpret_cast<const float4*>(&hs[p][bl][4]);
            const float2 hc = *reinterpret_cast<const float2*>(&hs[p][bl][8]);
            const ull h01 = pk(ha.x, ha.y);
            const ull h23 = pk(ha.z, ha.w);
            const ull h45 = pk(hb.x, hb.y);
            const ull h67 = pk(hb.z, hb.w);
            const ull h89 = pk(hc.x, hc.y);

            // two gates per lane, 5 fma2 each on natural pairs
            ull aLo = mul2(x1, ubLo);          // {x*u, b}
            aLo = fma2(wLo[0], h01, aLo);
            aLo = fma2(wLo[1], h23, aLo);
            aLo = fma2(wLo[2], h45, aLo);
            aLo = fma2(wLo[3], h67, aLo);
            aLo = fma2(wLo[4], h89, aLo);
            ull aHi = mul2(x1, ubHi);
            aHi = fma2(wHi[0], h01, aHi);
            aHi = fma2(wHi[1], h23, aHi);
            aHi = fma2(wHi[2], h45, aHi);
            aHi = fma2(wHi[3], h67, aHi);
            aHi = fma2(wHi[4], h89, aHi);

            const float2 vLo = upk(aLo);
            const float2 vHi = upk(aHi);
            const float gateLo = vLo.x + vLo.y;  // even: i/2   odd: g
            const float gateHi = vHi.x + vHi.y;  // even: f/2   odd: o/2

            const float tLo = tanha(gateLo);
            const float tHi = tanha(gateHi);

            // exchange partner's tanh values (even lanes receive tg, to)
            const float tx = __shfl_xor_sync(0xffffffffu, tLo, 1);
            const float ty = __shfl_xor_sync(0xffffffffu, tHi, 1);

            // even lanes: real recurrence (odd lanes same instrs, dead data)
            const float si = fmaf(0.5f, tLo, 0.5f);
            const float sf = fmaf(0.5f, tHi, 0.5f);
            c = fmaf(sf, c, si * tx);

            const float tc = tanha(c);
            const float hn2 = fmaf(ty, tc, tc);   // 2h = (tanh(o/2)+1)*tanh(c)

            if (half == 0) hs[p ^ 1][bl][r] = hn2;
            __syncthreads();
            p ^= 1;
        }
        xv = xn;
    }

    // ---- output: out[b] = sum_r c_r * W_lin[r] + b_lin ----
    float* scr = &hs[0][0][0];
    if (half == 0) scr[bl * 12 + r] = c * wlin;
    __syncthreads();
    if (tid < NB) {
        float s = b_lin[0];
#pragma unroll
        for (int j = 0; j < HDIM; j++) s += scr[tid * 12 + j];
        out[blockIdx.x * NB + tid] = s;
    }
}

extern "C" void kernel_launch(void* const* d_in, const int* in_sizes, int n_in,
                              void* d_out, int out_size) {
    const float* x     = (const float*)d_in[0];  // [B, T, 1]
    const float* W_ih  = (const float*)d_in[1];  // [4H, 1]
    const float* W_hh  = (const float*)d_in[2];  // [4H, H]
    const float* b_ih  = (const float*)d_in[3];  // [4H]
    const float* b_hh  = (const float*)d_in[4];  // [4H]
    const float* W_lin = (const float*)d_in[5];  // [1, H]
    const float* b_lin = (const float*)d_in[6];  // [1]
    float* out = (float*)d_out;                  // [B, 1]

    const int B = in_sizes[0] / T_STEPS;         // 8192
    const int blocks = B / NB;                   // 1024 blocks x 5 warps

    lstm2linear_kernel<<<blocks, NTH>>>(x, W_ih, W_hh, b_ih, b_hh,
                                        W_lin, b_lin, out);
}